// round 17
// baseline (speedup 1.0000x reference)
#include <cuda_runtime.h>
#include <cuda_bf16.h>
#include <cstdint>

#define DEVFN __device__ __forceinline__

constexpr int BN = 16;      // batch
constexpr int CI = 64;      // in channels
constexpr int CO = 64;      // out channels
constexpr int HW = 4096;    // 64x64
constexpr int OC = 18;      // offset channels

// Scratch (static device memory; zero-initialized at module load)
__device__ __align__(16) float g_xt [BN * HW * CI];       // x in NHWC
__device__ __align__(16) __nv_bfloat16 g_wbh[9 * 4096];   // w_dcn hi, per-tap SW128-swizzled [co][cin]
__device__ __align__(16) __nv_bfloat16 g_wbl[9 * 4096];   // w_dcn lo
__device__ __align__(16) __nv_bfloat16 g_wobh[9 * 2048];  // w_off hi, per-tap SW128 [oc(32,pad0)][cin]
__device__ __align__(16) __nv_bfloat16 g_wobl[9 * 2048];  // w_off lo
__device__ __align__(16) float4 g_cfw[BN * HW * 9];       // bilinear weights per (pix,tap)
__device__ __align__(16) int4   g_cfi[BN * HW * 9];       // clamped corner base offsets

DEVFN uint32_t smem_u32(const void* p) {
    uint32_t a;
    asm("{ .reg .u64 t; cvta.to.shared.u64 t, %1; cvt.u32.u64 %0, t; }" : "=r"(a) : "l"(p));
    return a;
}
// ---- ldmatrix / mma.sync (sm_80+ PTX, valid on plain sm_103 target) ----
DEVFN void ldm_x4(uint32_t* r, uint32_t addr) {
    asm volatile("ldmatrix.sync.aligned.m8n8.x4.shared.b16 {%0,%1,%2,%3}, [%4];"
                 : "=r"(r[0]), "=r"(r[1]), "=r"(r[2]), "=r"(r[3]) : "r"(addr));
}
DEVFN void ldm_x2(uint32_t* r, uint32_t addr) {
    asm volatile("ldmatrix.sync.aligned.m8n8.x2.shared.b16 {%0,%1}, [%2];"
                 : "=r"(r[0]), "=r"(r[1]) : "r"(addr));
}
DEVFN void mma_bf16(float* d, const uint32_t* a, const uint32_t* b) {
    asm volatile("mma.sync.aligned.m16n8k16.row.col.f32.bf16.bf16.f32 "
                 "{%0,%1,%2,%3}, {%4,%5,%6,%7}, {%8,%9}, {%0,%1,%2,%3};"
                 : "+f"(d[0]), "+f"(d[1]), "+f"(d[2]), "+f"(d[3])
                 : "r"(a[0]), "r"(a[1]), "r"(a[2]), "r"(a[3]), "r"(b[0]), "r"(b[1]));
}
DEVFN uint32_t sw128(uint32_t byte) { return byte ^ ((byte >> 3) & 0x70); }
DEVFN void split_store(char* smem_base, uint32_t sw, float2 v, int loOff) {
    __nv_bfloat162 h2 = __float22bfloat162_rn(v);
    float2 fh = __bfloat1622float2(h2);
    __nv_bfloat162 l2 = __float22bfloat162_rn(make_float2(v.x - fh.x, v.y - fh.y));
    *(uint32_t*)(smem_base + sw)         = *(uint32_t*)&h2;
    *(uint32_t*)(smem_base + loOff + sw) = *(uint32_t*)&l2;
}

// ---------------------------------------------------------------------------
// Weight prepack: bf16 hi/lo split + SW128 pre-swizzle for both convs.
// ---------------------------------------------------------------------------
__global__ void k_prepack(const float* __restrict__ wdcn, const float* __restrict__ woff) {
    int i = blockIdx.x * blockDim.x + threadIdx.x;
    if (i < 9 * 4096) {
        int t = i >> 12, r = i & 4095;
        int co = r >> 6, cin = r & 63;
        float w = wdcn[(co * CI + cin) * 9 + t];
        __nv_bfloat16 hi = __float2bfloat16(w);
        __nv_bfloat16 lo = __float2bfloat16(w - __bfloat162float(hi));
        uint32_t sw = sw128((uint32_t)(co * 128 + cin * 2));
        g_wbh[t * 4096 + (sw >> 1)] = hi;
        g_wbl[t * 4096 + (sw >> 1)] = lo;
    }
    int j = i - 9 * 4096;
    if (j >= 0 && j < 9 * OC * 64) {
        int t  = j / (OC * 64);
        int r  = j - t * (OC * 64);
        int oc = r >> 6, cin = r & 63;
        float w = woff[(oc * CI + cin) * 9 + t];
        __nv_bfloat16 hi = __float2bfloat16(w);
        __nv_bfloat16 lo = __float2bfloat16(w - __bfloat162float(hi));
        uint32_t sw = sw128((uint32_t)(oc * 128 + cin * 2));
        g_wobh[t * 2048 + (sw >> 1)] = hi;
        g_wobl[t * 2048 + (sw >> 1)] = lo;
    }
}

// ---------------------------------------------------------------------------
// NCHW -> NHWC transpose, float4 both sides. Block 32x8, tile 32ch x 128px.
// ---------------------------------------------------------------------------
__global__ void k_transpose(const float* __restrict__ x) {
    __shared__ float s[32][129];
    int b  = blockIdx.z;
    int c0 = blockIdx.y * 32;
    int p0 = blockIdx.x * 128;
    int tx = threadIdx.x, ty = threadIdx.y;       // 32 x 8
    int tid = ty * 32 + tx;
    const float* xb = x + (size_t)b * CI * HW;
    // load: 32 channels x 128 pixels, float4 along pixels
#pragma unroll
    for (int i = 0; i < 4; i++) {
        int c = ty + 8 * i;
        float4 v = *(const float4*)(xb + (size_t)(c0 + c) * HW + p0 + tx * 4);
        s[c][tx * 4]     = v.x;
        s[c][tx * 4 + 1] = v.y;
        s[c][tx * 4 + 2] = v.z;
        s[c][tx * 4 + 3] = v.w;
    }
    __syncthreads();
    // store: float4 along channels; 1024 float4 items, 4 per thread
    float* xtb = g_xt + (size_t)b * HW * CI;
#pragma unroll
    for (int i = 0; i < 4; i++) {
        int idx = tid + 256 * i;
        int px = idx >> 3, cg = idx & 7;
        float4 v = make_float4(s[cg * 4][px], s[cg * 4 + 1][px],
                               s[cg * 4 + 2][px], s[cg * 4 + 3][px]);
        *(float4*)(xtb + (size_t)(p0 + px) * CI + c0 + cg * 4) = v;
    }
}

// ---------------------------------------------------------------------------
// Offset conv (split-bf16 mma, N padded 18->32) + fused bilinear coeff.
// CTA = 256 thr, 128 px. Unchanged from R15 (validated).
// ---------------------------------------------------------------------------
__global__ __launch_bounds__(256) void k_offcoef(const float* __restrict__ boff) {
    __shared__ __align__(128) char smem[40960];
    uint32_t sb = smem_u32(smem);
    int tid = threadIdx.x, wid = tid >> 5, lane = tid & 31;
    int base = blockIdx.x * 128;
    int b    = base >> 12;
    int prow = base & 4095;
    const float* xtb = g_xt + (size_t)b * HW * CI;

    float acc[4][4];
#pragma unroll
    for (int ni = 0; ni < 4; ni++)
#pragma unroll
        for (int e = 0; e < 4; e++) acc[ni][e] = 0.f;

    for (int t = 0; t < 9; t++) {
        ((uint4*)(smem + 32768))[tid] = ((const uint4*)(g_wobh + t * 2048))[tid];
        ((uint4*)(smem + 36864))[tid] = ((const uint4*)(g_wobl + t * 2048))[tid];
        int dy = t / 3 - 1;
        int dx = t - (t / 3) * 3 - 1;
#pragma unroll 4
        for (int i = 0; i < 16; i++) {
            int p  = wid * 16 + i;
            int pp = prow + p;
            int y  = (pp >> 6) + dy;
            int x  = (pp & 63) + dx;
            float2 v = make_float2(0.f, 0.f);
            if (((unsigned)y < 64u) && ((unsigned)x < 64u))
                v = *((const float2*)(xtb + (((y << 6) + x) << 6)) + lane);
            split_store(smem, sw128((uint32_t)(p * 128 + lane * 4)), v, 16384);
        }
        __syncthreads();
#pragma unroll
        for (int k16 = 0; k16 < 4; k16++) {
            uint32_t ah[4], al[4];
            {
                int row = wid * 16 + (lane & 15);
                uint32_t byte = sw128((uint32_t)(row * 128 + k16 * 32 + ((lane >> 4) << 4)));
                ldm_x4(ah, sb + byte);
                ldm_x4(al, sb + 16384 + byte);
            }
            uint32_t bh[4][2], bl[4][2];
#pragma unroll
            for (int ni = 0; ni < 4; ni++) {
                int n = ni * 8 + (lane & 7);
                uint32_t byte = sw128((uint32_t)(n * 128 + k16 * 32 + (((lane >> 3) & 1) << 4)));
                ldm_x2(bh[ni], sb + 32768 + byte);
                ldm_x2(bl[ni], sb + 36864 + byte);
            }
#pragma unroll
            for (int ni = 0; ni < 4; ni++) {
                mma_bf16(acc[ni], ah, bh[ni]);
                mma_bf16(acc[ni], al, bh[ni]);
                mma_bf16(acc[ni], ah, bl[ni]);
            }
        }
        __syncthreads();
    }
    float* sAcc = (float*)smem;
    int r = lane >> 2, g = lane & 3;
#pragma unroll
    for (int ni = 0; ni < 4; ni++) {
        int co = ni * 8 + g * 2;
        int px = wid * 16 + r;
        sAcc[px * 36 + co]           = acc[ni][0];
        sAcc[px * 36 + co + 1]       = acc[ni][1];
        sAcc[(px + 8) * 36 + co]     = acc[ni][2];
        sAcc[(px + 8) * 36 + co + 1] = acc[ni][3];
    }
    __syncthreads();
#pragma unroll
    for (int it = 0; it < 5; it++) {
        int idx = tid + 256 * it;              // 1152 items
        if (idx < 128 * 9) {
            int p = idx / 9;
            int t = idx - p * 9;
            int pp = prow + p;
            float oy = sAcc[p * 36 + 2 * t]     + boff[2 * t];
            float ox = sAcc[p * 36 + 2 * t + 1] + boff[2 * t + 1];
            float py  = (float)((pp >> 6) + t / 3 - 1) + oy;
            float pxx = (float)((pp & 63) + t % 3 - 1) + ox;
            float y0f = floorf(py), x0f = floorf(pxx);
            float fy = py - y0f, fx = pxx - x0f;
            int y0 = (int)y0f, x0 = (int)x0f;
            float vy0 = ((unsigned)y0 < 64u) ? 1.f : 0.f;
            float vy1 = ((unsigned)(y0 + 1) < 64u) ? 1.f : 0.f;
            float vx0 = ((unsigned)x0 < 64u) ? 1.f : 0.f;
            float vx1 = ((unsigned)(x0 + 1) < 64u) ? 1.f : 0.f;
            float gy0 = 1.f - fy, gx0 = 1.f - fx;
            int gi = (base + p) * 9 + t;
            g_cfw[gi] = make_float4(gy0 * gx0 * vy0 * vx0, gy0 * fx * vy0 * vx1,
                                    fy * gx0 * vy1 * vx0,  fy * fx * vy1 * vx1);
            int yc0 = min(max(y0, 0), 63),     yc1 = min(max(y0 + 1, 0), 63);
            int xc0 = min(max(x0, 0), 63),     xc1 = min(max(x0 + 1, 0), 63);
            g_cfi[gi] = make_int4((((yc0 << 6) + xc0) << 6), (((yc0 << 6) + xc1) << 6),
                                  (((yc1 << 6) + xc0) << 6), (((yc1 << 6) + xc1) << 6));
        }
    }
}

// ---------------------------------------------------------------------------
// Deformable conv: split-bf16 mma.sync GEMM, software-pipelined.
// CTA = 128 thr, 64 px x 64 co. A tiles double-buffered so gather(t+1)
// overlaps GEMM(t) without a barrier between them; B restaged in a tiny
// second barrier region.
// smem: A0h[0,8K) A0l[8K,16K) A1h[16K,24K) A1l[24K,32K) Bh[32K,40K) Bl[40K,48K)
// ---------------------------------------------------------------------------
__global__ __launch_bounds__(128) void k_deform(const float* __restrict__ bdcn,
                                                float* __restrict__ out) {
    __shared__ __align__(128) char smem[49152];
    uint32_t sb = smem_u32(smem);
    int tid = threadIdx.x, wid = tid >> 5, lane = tid & 31;
    int base = blockIdx.x * 64;
    int b    = base >> 12;
    int prow = base & 4095;
    const float* xtb = g_xt + (size_t)b * HW * CI;
    int wm = wid >> 1, wn = wid & 1;          // warp grid 2(m) x 2(n)
    int mbase = wm * 32, nbase = wn * 32;

    float acc[2][4][4];
#pragma unroll
    for (int mi = 0; mi < 2; mi++)
#pragma unroll
        for (int ni = 0; ni < 4; ni++)
#pragma unroll
            for (int e = 0; e < 4; e++) acc[mi][ni][e] = 0.f;

    // ---- prologue: stage B(0) and gather(0) into A stage 0 ----
    {
        const uint4* sh = (const uint4*)(g_wbh);
        const uint4* sl = (const uint4*)(g_wbl);
#pragma unroll
        for (int r = 0; r < 4; r++) {
            ((uint4*)(smem + 32768))[tid + 128 * r] = sh[tid + 128 * r];
            ((uint4*)(smem + 40960))[tid + 128 * r] = sl[tid + 128 * r];
        }
    }
#pragma unroll 4
    for (int i = 0; i < 16; i++) {
        int p = wid * 16 + i;
        int ci = (base + p) * 9;
        float4 cw = g_cfw[ci];
        int4  ii = g_cfi[ci];
        float2 v00 = *((const float2*)(xtb + ii.x) + lane);
        float2 v01 = *((const float2*)(xtb + ii.y) + lane);
        float2 v10 = *((const float2*)(xtb + ii.z) + lane);
        float2 v11 = *((const float2*)(xtb + ii.w) + lane);
        float2 v;
        v.x = cw.x * v00.x + cw.y * v01.x + cw.z * v10.x + cw.w * v11.x;
        v.y = cw.x * v00.y + cw.y * v01.y + cw.z * v10.y + cw.w * v11.y;
        split_store(smem, sw128((uint32_t)(p * 128 + lane * 4)), v, 8192);
    }
    __syncthreads();

    for (int t = 0; t < 9; t++) {
        int s = t & 1;
        uint32_t sa = sb + s * 16384;
        // ---- GEMM(t) from A[s], B (both ready) ----
#pragma unroll
        for (int k16 = 0; k16 < 4; k16++) {
            uint32_t ah[2][4], al[2][4];
#pragma unroll
            for (int mi = 0; mi < 2; mi++) {
                int row = mbase + mi * 16 + (lane & 15);
                uint32_t byte = sw128((uint32_t)(row * 128 + k16 * 32 + ((lane >> 4) << 4)));
                ldm_x4(ah[mi], sa + byte);
                ldm_x4(al[mi], sa + 8192 + byte);
            }
            uint32_t bh[4][2], bl[4][2];
#pragma unroll
            for (int ni = 0; ni < 4; ni++) {
                int n = nbase + ni * 8 + (lane & 7);
                uint32_t byte = sw128((uint32_t)(n * 128 + k16 * 32 + (((lane >> 3) & 1) << 4)));
                ldm_x2(bh[ni], sb + 32768 + byte);
                ldm_x2(bl[ni], sb + 40960 + byte);
            }
#pragma unroll
            for (int mi = 0; mi < 2; mi++)
#pragma unroll
                for (int ni = 0; ni < 4; ni++) {
                    mma_bf16(acc[mi][ni], ah[mi], bh[ni]);
                    mma_bf16(acc[mi][ni], al[mi], bh[ni]);
                    mma_bf16(acc[mi][ni], ah[mi], bl[ni]);
                }
        }
        // ---- gather(t+1) into A[s^1] (disjoint smem; no barrier needed) ----
        if (t < 8) {
            char* astg = smem + (s ^ 1) * 16384;
#pragma unroll 4
            for (int i = 0; i < 16; i++) {
                int p = wid * 16 + i;
                int ci = (base + p) * 9 + t + 1;
                float4 cw = g_cfw[ci];
                int4  ii = g_cfi[ci];
                float2 v00 = *((const float2*)(xtb + ii.x) + lane);
                float2 v01 = *((const float2*)(xtb + ii.y) + lane);
                float2 v10 = *((const float2*)(xtb + ii.z) + lane);
                float2 v11 = *((const float2*)(xtb + ii.w) + lane);
                float2 v;
                v.x = cw.x * v00.x + cw.y * v01.x + cw.z * v10.x + cw.w * v11.x;
                v.y = cw.x * v00.y + cw.y * v01.y + cw.z * v10.y + cw.w * v11.y;
                split_store(astg, sw128((uint32_t)(p * 128 + lane * 4)), v, 8192);
            }
        }
        __syncthreads();
        // ---- tiny region: restage B(t+1) (GEMM(t) finished at the barrier) ----
        if (t < 8) {
            const uint4* sh = (const uint4*)(g_wbh + (t + 1) * 4096);
            const uint4* sl = (const uint4*)(g_wbl + (t + 1) * 4096);
#pragma unroll
            for (int r = 0; r < 4; r++) {
                ((uint4*)(smem + 32768))[tid + 128 * r] = sh[tid + 128 * r];
                ((uint4*)(smem + 40960))[tid + 128 * r] = sl[tid + 128 * r];
            }
            __syncthreads();
        }
    }
    // ---- epilogue: bounce acc through smem [co][68] for coalesced stores ----
    float* sAcc = (float*)smem;
    int r = lane >> 2, g = lane & 3;
#pragma unroll
    for (int mi = 0; mi < 2; mi++)
#pragma unroll
        for (int ni = 0; ni < 4; ni++) {
            int co = nbase + ni * 8 + g * 2;
            int px = mbase + mi * 16 + r;
            sAcc[co * 68 + px]             = acc[mi][ni][0];
            sAcc[(co + 1) * 68 + px]       = acc[mi][ni][1];
            sAcc[co * 68 + px + 8]         = acc[mi][ni][2];
            sAcc[(co + 1) * 68 + px + 8]   = acc[mi][ni][3];
        }
    __syncthreads();
    float* ob = out + (size_t)b * CO * HW + prow;
#pragma unroll
    for (int it = 0; it < 8; it++) {
        int idx = tid + 128 * it;          // 1024 float4 total
        int row = idx >> 4, c4 = idx & 15;
        float4 v = *(float4*)(sAcc + row * 68 + c4 * 4);
        float bias = bdcn[row];
        v.x += bias; v.y += bias; v.z += bias; v.w += bias;
        *(float4*)(ob + (size_t)row * HW + c4 * 4) = v;
    }
}

// ---------------------------------------------------------------------------
extern "C" void kernel_launch(void* const* d_in, const int* in_sizes, int n_in,
                              void* d_out, int out_size) {
    const float* x     = (const float*)d_in[0];
    const float* w_off = (const float*)d_in[1];
    const float* b_off = (const float*)d_in[2];
    const float* w_dcn = (const float*)d_in[3];
    const float* b_dcn = (const float*)d_in[4];
    (void)in_sizes; (void)n_in; (void)out_size;

    int prepack_total = 9 * 4096 + 9 * OC * 64;
    k_prepack<<<(prepack_total + 127) / 128, 128>>>(w_dcn, w_off);
    k_transpose<<<dim3(HW / 128, CI / 32, BN), dim3(32, 8)>>>(x);
    k_offcoef<<<BN * HW / 128, 256>>>(b_off);
    k_deform<<<BN * HW / 64, 128>>>(b_dcn, (float*)d_out);
}